// round 14
// baseline (speedup 1.0000x reference)
#include <cuda_runtime.h>
#include <cuda_fp16.h>
#include <cstdint>
#include <math.h>

// Problem constants
#define BB 4
#define TT 8192
#define HH 16
#define DD 64
#define CC 128                 // chunk length
#define NC (TT/CC)             // 64 chunks per sequence
#define BHN (BB*HH)            // 64 (b,h) pairs
#define NCHUNKS (BHN*NC)       // 4096 total chunks
#define EPSV 1e-6f

// Scratch (fp16): per-chunk M^T (e-major), converted in-place to exclusive prefix S_prev^T
__device__ __half g_M16[(size_t)NCHUNKS * DD * DD];   // 32 MB
__device__ float  g_z[(size_t)NCHUNKS * DD];          // 1 MB (fp32)

__device__ __forceinline__ float phi_f(float x) {
    return x > 0.f ? x + 1.f : expf(x);   // elu(x)+1
}

__device__ __forceinline__ void mma16(float* d, const uint32_t* a, const uint32_t* b) {
    asm volatile(
        "mma.sync.aligned.m16n8k16.row.col.f32.f16.f16.f32 "
        "{%0,%1,%2,%3}, {%4,%5,%6,%7}, {%8,%9}, {%0,%1,%2,%3};"
        : "+f"(d[0]), "+f"(d[1]), "+f"(d[2]), "+f"(d[3])
        : "r"(a[0]), "r"(a[1]), "r"(a[2]), "r"(a[3]), "r"(b[0]), "r"(b[1]));
}

__device__ __forceinline__ uint32_t packh2(float lo, float hi) {
    __half2 h = __floats2half2_rn(lo, hi);
    return *(uint32_t*)&h;
}
__device__ __forceinline__ uint32_t sm32(const void* p) {
    return (uint32_t)__cvta_generic_to_shared(p);
}
__device__ __forceinline__ void ldsm4(uint32_t* r, uint32_t a) {
    asm volatile("ldmatrix.sync.aligned.m8n8.x4.shared.b16 {%0,%1,%2,%3}, [%4];"
                 : "=r"(r[0]), "=r"(r[1]), "=r"(r[2]), "=r"(r[3]) : "r"(a));
}
__device__ __forceinline__ void ldsm4t(uint32_t* r, uint32_t a) {
    asm volatile("ldmatrix.sync.aligned.m8n8.x4.trans.shared.b16 {%0,%1,%2,%3}, [%4];"
                 : "=r"(r[0]), "=r"(r[1]), "=r"(r[2]), "=r"(r[3]) : "r"(a));
}

// ---------------------------------------------------------------------------
// Kernel 1: per-chunk M^T[e][d] = sum_t V[t][e] phiK[t][d], z_c = sum_t phiK.
// K,V staged natural row-major via float4 LDG; ldmatrix.trans for operands.
// grid = NCHUNKS, block = 256.
// ---------------------------------------------------------------------------
#define S1 72     // 144B row stride: /16 ok, 36 words == 4 mod 32 -> conflict-free
#define SMEM1 (2*128*S1*2 + 16*64*4 + 16)

__global__ void __launch_bounds__(256, 4) k1_kv(const float* __restrict__ kin,
                                                const float* __restrict__ vin) {
    extern __shared__ __align__(16) char smraw[];
    __half* sK1 = (__half*)smraw;              // [128 t][72] phiK
    __half* sV1 = sK1 + 128 * S1;              // [128 t][72] V
    float* sZp = (float*)(sV1 + 128 * S1);     // [16][64] z partials

    int g = blockIdx.x;
    int bh = g >> 6, c = g & 63;
    int b = bh >> 4, h = bh & 15;
    int t0 = c * CC;
    int tid = threadIdx.x;
    int q4 = tid & 15, rg = tid >> 4;          // col-quad, row group

    const size_t rowstride = (size_t)HH * DD;
    size_t base = ((size_t)b * TT + t0) * rowstride + (size_t)h * DD + q4 * 4;

    float z0 = 0.f, z1 = 0.f, z2 = 0.f, z3 = 0.f;
#pragma unroll 2
    for (int p = 0; p < 8; ++p) {
        int t = p * 16 + rg;
        size_t a = base + (size_t)t * rowstride;
        float4 kk = *(const float4*)(kin + a);
        float4 vv = *(const float4*)(vin + a);
        float p0 = phi_f(kk.x), p1 = phi_f(kk.y), p2 = phi_f(kk.z), p3 = phi_f(kk.w);
        z0 += p0; z1 += p1; z2 += p2; z3 += p3;
        __half* kd = sK1 + t * S1 + q4 * 4;
        *(uint32_t*)kd = packh2(p0, p1);
        *(uint32_t*)(kd + 2) = packh2(p2, p3);
        __half* vd = sV1 + t * S1 + q4 * 4;
        *(uint32_t*)vd = packh2(vv.x, vv.y);
        *(uint32_t*)(vd + 2) = packh2(vv.z, vv.w);
    }
    {
        float* zr = sZp + rg * 64 + q4 * 4;
        zr[0] = z0; zr[1] = z1; zr[2] = z2; zr[3] = z3;
    }
    __syncthreads();
    if (tid < 64) {
        float s = 0.f;
#pragma unroll
        for (int r = 0; r < 16; ++r) s += sZp[r * 64 + tid];
        g_z[(size_t)g * 64 + tid] = s;
    }

    int w = tid >> 5, lane = tid & 31;
    int gid = lane >> 2, tig = lane & 3;
    int row8 = lane & 7, seg = lane >> 3;
    int m0 = (w & 3) * 16;          // e-band (rows of M^T)
    int d0 = (w >> 2) * 32;         // d-half (cols of M^T)

    // A = V^T (m=e,k=t) from [t][e] storage: trans, m<-seg&1, k<-seg>>1
    uint32_t aVb = sm32(sV1 + (row8 + ((seg >> 1) << 3)) * S1 + m0 + ((seg & 1) << 3));
    // B = K^T (n=d,k=t) from [t][d] storage: trans, k<-seg&1, n<-seg>>1
    uint32_t bKb = sm32(sK1 + (row8 + ((seg & 1) << 3)) * S1 + d0 + ((seg >> 1) << 3));

    float acc[4][4];
#pragma unroll
    for (int i = 0; i < 4; i++)
#pragma unroll
        for (int j = 0; j < 4; j++) acc[i][j] = 0.f;

#pragma unroll
    for (int ks = 0; ks < 8; ++ks) {
        uint32_t koff = (uint32_t)(16 * ks * S1) * 2;
        uint32_t a[4];
        ldsm4t(a, aVb + koff);
#pragma unroll
        for (int np = 0; np < 2; ++np) {
            uint32_t bf4[4];
            ldsm4t(bf4, bKb + koff + np * 32);
            mma16(acc[2 * np], a, bf4 + 0);
            mma16(acc[2 * np + 1], a, bf4 + 2);
        }
    }

    __half* Mout = g_M16 + (size_t)g * DD * DD;   // [e][d]
#pragma unroll
    for (int nt = 0; nt < 4; ++nt) {
        int c0 = d0 + nt * 8 + 2 * tig;
        int r0 = m0 + gid;
        *(uint32_t*)(Mout + (size_t)r0 * DD + c0) = packh2(acc[nt][0], acc[nt][1]);
        *(uint32_t*)(Mout + (size_t)(r0 + 8) * DD + c0) = packh2(acc[nt][2], acc[nt][3]);
    }
}

// ---------------------------------------------------------------------------
// Kernel 2: exclusive prefix over chunks (fp16 data, fp32 running sums)
// ---------------------------------------------------------------------------
__global__ void __launch_bounds__(256) k2_scan() {
    int bh = blockIdx.x >> 3;
    int seg = blockIdx.x & 7;
    int u = seg * 256 + threadIdx.x;               // uint32 index, 2048 per chunk
    uint32_t* base = (uint32_t*)g_M16 + (size_t)bh * 64 * 2048 + u;

    uint32_t vals[64];
#pragma unroll
    for (int c = 0; c < 64; ++c) vals[c] = base[(size_t)c * 2048];

    float r0 = 0.f, r1 = 0.f;
#pragma unroll
    for (int c = 0; c < 64; ++c) {
        __half2 hv = *(__half2*)&vals[c];
        float a0 = __low2float(hv), a1 = __high2float(hv);
        vals[c] = packh2(r0, r1);
        r0 += a0;
        r1 += a1;
    }
#pragma unroll
    for (int c = 0; c < 64; ++c) base[(size_t)c * 2048] = vals[c];
}

__global__ void __launch_bounds__(64) k2_scanz() {
    int bh = blockIdx.x;
    size_t base = (size_t)bh * 64 * 64 + threadIdx.x;

    float vals[64];
#pragma unroll
    for (int c = 0; c < 64; ++c) vals[c] = g_z[base + (size_t)c * 64];
    float run = 0.f;
#pragma unroll
    for (int c = 0; c < 64; ++c) {
        float t = vals[c];
        vals[c] = run;
        run += t;
    }
#pragma unroll
    for (int c = 0; c < 64; ++c) g_z[base + (size_t)c * 64] = vals[c];
}

// ---------------------------------------------------------------------------
// Kernel 3: 256 threads, 8 warps, warp owns band bo = wid<4 ? wid : 11-wid.
//  - Q staged in smem (R12 config: coalesced once, afr hoisted, qz from smem)
//  - K natural [s][d]: non-trans ldsm
//  - V natural [t][e]: ldsm.trans (no transposed STS)
//  - S_prev^T fp16: uint4 copy, non-trans ldsm
//  - all staging via float4 LDG, unroll 2 (limit front-batch queue burst)
// ---------------------------------------------------------------------------
#define S3 72

#define H_SQ   0
#define H_SK   (H_SQ + 128*S3)       // 9216
#define H_SV   (H_SK + 128*S3)       // 18432
#define H_SST  (H_SV + 128*S3)       // 27648
#define H_END  (H_SST + 64*S3)       // 32256 halfs
#define SMEM3  (H_END*2 + 64*4 + 16)

__global__ void __launch_bounds__(256, 3) k3_out(const float* __restrict__ qin,
                                                 const float* __restrict__ kin,
                                                 const float* __restrict__ vin,
                                                 float* __restrict__ out) {
    extern __shared__ __align__(16) char smraw[];
    __half* sQ  = (__half*)smraw + H_SQ;    // [128 t][72]  phiQ
    __half* sK  = (__half*)smraw + H_SK;    // [128 s][72]  phiK
    __half* sV  = (__half*)smraw + H_SV;    // [128 t][72]  V (natural)
    __half* sST = (__half*)smraw + H_SST;   // [64 e][72]   S_prev^T
    float* sZ = (float*)((__half*)smraw + H_END);  // [64]

    int g = blockIdx.x;
    int bh = g >> 6, c = g & 63;
    int b = bh >> 4, h = bh & 15;
    int t0 = c * CC;
    int tid = threadIdx.x;

    const size_t rowstride = (size_t)HH * DD;

    // ---- staging: Q,K (phi), V natural row-major (float4); S^T (uint4) ----
    {
        int q4 = tid & 15, rg = tid >> 4;
        size_t base = ((size_t)b * TT + t0) * rowstride + (size_t)h * DD + q4 * 4;
#pragma unroll 2
        for (int p = 0; p < 8; ++p) {
            int t = p * 16 + rg;
            size_t a = base + (size_t)t * rowstride;
            float4 qq = *(const float4*)(qin + a);
            float4 kk = *(const float4*)(kin + a);
            float4 vv = *(const float4*)(vin + a);
            __half* qd = sQ + t * S3 + q4 * 4;
            *(uint32_t*)qd = packh2(phi_f(qq.x), phi_f(qq.y));
            *(uint32_t*)(qd + 2) = packh2(phi_f(qq.z), phi_f(qq.w));
            __half* kd = sK + t * S3 + q4 * 4;
            *(uint32_t*)kd = packh2(phi_f(kk.x), phi_f(kk.y));
            *(uint32_t*)(kd + 2) = packh2(phi_f(kk.z), phi_f(kk.w));
            __half* vd = sV + t * S3 + q4 * 4;
            *(uint32_t*)vd = packh2(vv.x, vv.y);
            *(uint32_t*)(vd + 2) = packh2(vv.z, vv.w);
        }
        const uint4* Sp4 = (const uint4*)(g_M16 + (size_t)g * 4096);
#pragma unroll
        for (int i = tid; i < 512; i += 256) {
            uint4 wv = Sp4[i];
            int e = i >> 3, dh = (i & 7) * 8;
            *(uint4*)&sST[e * S3 + dh] = wv;
        }
        if (tid < 64) sZ[tid] = g_z[(size_t)g * 64 + tid];
    }
    __syncthreads();

    int wid = tid >> 5, lane = tid & 31;
    int gid = lane >> 2, tig = lane & 3;
    int row8 = lane & 7, seg = lane >> 3;
    int bo = (wid < 4) ? wid : (11 - wid);   // SMSP-balanced band assignment
    int r_lo = bo * 16 + gid, r_hi = r_lo + 8;

    // LDSM bases
    // A from sQ [m][k] rows: m<-seg&1, k<-seg&2
    uint32_t aQb = sm32(sQ + (bo * 16 + row8 + ((seg & 1) << 3)) * S3 + ((seg & 2) << 2));
    // non-trans B ([n][k] rows): n<-seg>>1, k<-seg&1
    uint32_t sTb = sm32(sST + (row8 + ((seg >> 1) << 3)) * S3 + ((seg & 1) << 3));
    uint32_t sKb = sm32(sK + (row8 + ((seg >> 1) << 3)) * S3 + ((seg & 1) << 3));
    // trans B ([k][n] rows): k<-seg&1, n<-seg>>1
    uint32_t sVb = sm32(sV + (row8 + ((seg & 1) << 3)) * S3 + ((seg >> 1) << 3));

    // ---- Q a-fragments: loaded once, reused by Q@S and all QK tiles ----
    uint32_t afr[4][4];
#pragma unroll
    for (int ks = 0; ks < 4; ++ks) ldsm4(afr[ks], aQb + ks * 32);

    float acc[8][4];
#pragma unroll
    for (int i = 0; i < 8; i++)
#pragma unroll
        for (int j = 0; j < 4; j++) acc[i][j] = 0.f;

    // ---- phase 1: acc = phiQ @ S_prev ----
#pragma unroll
    for (int ks = 0; ks < 4; ++ks) {
#pragma unroll
        for (int ntp = 0; ntp < 4; ++ntp) {
            uint32_t bf4[4];
            ldsm4(bf4, sTb + (uint32_t)(16 * ntp * S3) * 2 + ks * 32);
            mma16(acc[2 * ntp], afr[ks], bf4 + 0);
            mma16(acc[2 * ntp + 1], afr[ks], bf4 + 2);
        }
    }

    // ---- phase 2: qz = phiQ . z_prev (from smem) ----
    float qlo = 0.f, qhi = 0.f;
#pragma unroll
    for (int dd = 0; dd < 16; ++dd) {
        int d2 = tig * 16 + dd;
        float zv = sZ[d2];
        qlo += __half2float(sQ[r_lo * S3 + d2]) * zv;
        qhi += __half2float(sQ[r_hi * S3 + d2]) * zv;
    }
    qlo += __shfl_xor_sync(0xffffffffu, qlo, 1);
    qlo += __shfl_xor_sync(0xffffffffu, qlo, 2);
    qhi += __shfl_xor_sync(0xffffffffu, qhi, 1);
    qhi += __shfl_xor_sync(0xffffffffu, qhi, 2);

    // ---- phase 3: per 16-col k-tile: QK -> mask -> pack -> A@V ----
    float rs_lo = 0.f, rs_hi = 0.f;
#pragma unroll 2
    for (int j = 0; j <= bo; ++j) {
        float acc8[2][4];
#pragma unroll
        for (int u = 0; u < 2; ++u)
#pragma unroll
            for (int i = 0; i < 4; ++i) acc8[u][i] = 0.f;

        uint32_t jkoff = (uint32_t)(16 * j * S3) * 2;
#pragma unroll
        for (int ks = 0; ks < 4; ++ks) {
            uint32_t bf4[4];
            ldsm4(bf4, sKb + jkoff + ks * 32);
            mma16(acc8[0], afr[ks], bf4 + 0);
            mma16(acc8[1], afr[ks], bf4 + 2);
        }

        // mask (col <= row), rowsum, pack acc -> a-fragment (layout-exact)
        int cb0 = 16 * j + 2 * tig;
        int cb1 = cb0 + 8;
        float A00 = (cb0     <= r_lo) ? acc8[0][0] : 0.f;
        float A01 = (cb0 + 1 <= r_lo) ? acc8[0][1] : 0.f;
        float A02 = (cb0     <= r_hi) ? acc8[0][2] : 0.f;
        float A03 = (cb0 + 1 <= r_hi) ? acc8[0][3] : 0.f;
        float A10 = (cb1     <= r_lo) ? acc8[1][0] : 0.f;
        float A11 = (cb1 + 1 <= r_lo) ? acc8[1][1] : 0.f;
        float A12 = (cb1     <= r_hi) ? acc8[1][2] : 0.f;
        float A13 = (cb1 + 1 <= r_hi) ? acc8[1][3] : 0.f;
        rs_lo += A00 + A01 + A10 + A11;
        rs_hi += A02 + A03 + A12 + A13;
        uint32_t aA[4];
        aA[0] = packh2(A00, A01);
        aA[1] = packh2(A02, A03);
        aA[2] = packh2(A10, A11);
        aA[3] = packh2(A12, A13);

        // A@V: k16-range = s in [16j, 16j+16), V accessed transposed via ldsm.trans
#pragma unroll
        for (int ntp = 0; ntp < 4; ++ntp) {
            uint32_t bf4[4];
            ldsm4t(bf4, sVb + jkoff + (uint32_t)(16 * ntp) * 2);
            mma16(acc[2 * ntp], aA, bf4 + 0);
            mma16(acc[2 * ntp + 1], aA, bf4 + 2);
        }
    }

    rs_lo += __shfl_xor_sync(0xffffffffu, rs_lo, 1);
    rs_lo += __shfl_xor_sync(0xffffffffu, rs_lo, 2);
    rs_hi += __shfl_xor_sync(0xffffffffu, rs_hi, 1);
    rs_hi += __shfl_xor_sync(0xffffffffu, rs_hi, 2);

    // ---- epilogue ----
    float inv_lo = 1.f / (rs_lo + qlo + EPSV);
    float inv_hi = 1.f / (rs_hi + qhi + EPSV);
    size_t obase = ((size_t)b * TT + t0) * rowstride + (size_t)h * DD;
#pragma unroll
    for (int nt = 0; nt < 8; ++nt) {
        int c0 = nt * 8 + 2 * tig;
        *(float2*)(out + obase + (size_t)r_lo * rowstride + c0) =
            make_float2(acc[nt][0] * inv_lo, acc[nt][1] * inv_lo);
        *(float2*)(out + obase + (size_t)r_hi * rowstride + c0) =
            make_float2(acc[nt][2] * inv_hi, acc[nt][3] * inv_hi);
    }
}

// ---------------------------------------------------------------------------
extern "C" void kernel_launch(void* const* d_in, const int* in_sizes, int n_in,
                              void* d_out, int out_size) {
    const float* q = (const float*)d_in[0];
    const float* k = (const float*)d_in[1];
    const float* v = (const float*)d_in[2];
    float* out = (float*)d_out;

    cudaFuncSetAttribute(k1_kv, cudaFuncAttributeMaxDynamicSharedMemorySize, SMEM1);
    cudaFuncSetAttribute(k3_out, cudaFuncAttributeMaxDynamicSharedMemorySize, SMEM3);

    k1_kv<<<NCHUNKS, 256, SMEM1>>>(k, v);
    k2_scan<<<BHN * 8, 256>>>();
    k2_scanz<<<BHN, 64>>>();
    k3_out<<<NCHUNKS, 256, SMEM3>>>(q, k, v, out);
}